// round 7
// baseline (speedup 1.0000x reference)
#include <cuda_runtime.h>
#include <cuda_fp16.h>
#include <cstdint>

// ---------------------------------------------------------------------------
// Problem dims
// ---------------------------------------------------------------------------
#define BATCH   2048
#define IN_DIM  4096   // K
#define OUT_DIM 4096   // N

// Scratch (static __device__ = sanctioned mechanism).
__device__ __align__(256) __half g_W_h[(size_t)IN_DIM * OUT_DIM];  // [K,N] fp16 (32MB)
__device__ __align__(256) __half g_A_h[(size_t)BATCH * IN_DIM];    // [M,K] fp16 (16MB)
__device__ int g_ticket;                                            // persistent-GEMM work counter

// ---------------------------------------------------------------------------
// Kernel 1 (fused prep): blocks [0,4096) decode W, [4096,8192) convert A.
// ---------------------------------------------------------------------------
#define DEC_BLOCKS 4096
#define CNV_BLOCKS 4096

__global__ __launch_bounds__(256) void prep_kernel(const int4* __restrict__ idx,
                                                   const float* __restrict__ mean,
                                                   const float4* __restrict__ x) {
    const int b = blockIdx.x;
    if (b < DEC_BLOCKS) {
        __shared__ float sm[IN_DIM];
        #pragma unroll
        for (int i = threadIdx.x; i < IN_DIM; i += 256) sm[i] = mean[i];
        __syncthreads();

        const size_t base = (size_t)b * (256 * 4) + threadIdx.x;  // int4 units
        int4 v[4];
        #pragma unroll
        for (int p = 0; p < 4; p++) v[p] = idx[base + (size_t)p * 256];
        #pragma unroll
        for (int p = 0; p < 4; p++) {
            __half2 lo = __floats2half2_rn(sm[v[p].x], sm[v[p].y]);
            __half2 hi = __floats2half2_rn(sm[v[p].z], sm[v[p].w]);
            uint2 pk;
            pk.x = *reinterpret_cast<uint32_t*>(&lo);
            pk.y = *reinterpret_cast<uint32_t*>(&hi);
            reinterpret_cast<uint2*>(g_W_h)[base + (size_t)p * 256] = pk;
        }
    } else {
        if (b == DEC_BLOCKS && threadIdx.x == 0) g_ticket = 0;  // reset before GEMM
        int t = (b - DEC_BLOCKS) * 256 + threadIdx.x;
        float4 v0 = x[2 * t];
        float4 v1 = x[2 * t + 1];
        __half2 h0 = __floats2half2_rn(v0.x, v0.y);
        __half2 h1 = __floats2half2_rn(v0.z, v0.w);
        __half2 h2 = __floats2half2_rn(v1.x, v1.y);
        __half2 h3 = __floats2half2_rn(v1.z, v1.w);
        uint4 pk;
        pk.x = *reinterpret_cast<uint32_t*>(&h0);
        pk.y = *reinterpret_cast<uint32_t*>(&h1);
        pk.z = *reinterpret_cast<uint32_t*>(&h2);
        pk.w = *reinterpret_cast<uint32_t*>(&h3);
        reinterpret_cast<uint4*>(g_A_h)[t] = pk;
    }
}

// ---------------------------------------------------------------------------
// Kernel 2: persistent fp16 GEMM (fp32 accum) + bias. mma.sync + ldmatrix.
// Block tile 128x128, 4 warps (2x2), warp tile 64x64, BK=32, 4-stage cp.async,
// 296 persistent CTAs (2/SM). Inner loop: ALL 16 LDSM (both ks halves) are
// issued before the 64 MMAs, so LDSM latency is paid once per kt and the
// ks=1 operands land under the ks=0 MMA block.
// ---------------------------------------------------------------------------
#define BM 128
#define BN 128
#define BK 32
#define KT (IN_DIM / BK)        // 128
#define NTILES ((BATCH / BM) * (OUT_DIM / BN))   // 512
#define NWORKERS 296
#define STAGES 4
#define LDA_S 40                // A smem row stride (halves): 80B
#define LDB_S 136               // B smem row stride (halves): 272B
#define A_STAGE_H (BM * LDA_S)  // 5120
#define B_STAGE_H (BK * LDB_S)  // 4352
#define STAGE_H   (A_STAGE_H + B_STAGE_H)
#define SMEM_BYTES (STAGES * STAGE_H * 2)   // 75776 B (2 CTAs/SM: 151KB < 228KB)

__device__ __forceinline__ void cp_async16(__half* smem_dst, const __half* gmem_src) {
    uint32_t s = (uint32_t)__cvta_generic_to_shared(smem_dst);
    asm volatile("cp.async.cg.shared.global [%0], [%1], 16;\n" :: "r"(s), "l"(gmem_src));
}
__device__ __forceinline__ void cp_async_commit() {
    asm volatile("cp.async.commit_group;\n" ::);
}
template <int N>
__device__ __forceinline__ void cp_async_wait() {
    asm volatile("cp.async.wait_group %0;\n" :: "n"(N));
}
__device__ __forceinline__ void ldmatrix_x4(uint32_t* r, const __half* p) {
    uint32_t a = (uint32_t)__cvta_generic_to_shared(p);
    asm volatile("ldmatrix.sync.aligned.m8n8.x4.shared.b16 {%0,%1,%2,%3}, [%4];"
                 : "=r"(r[0]), "=r"(r[1]), "=r"(r[2]), "=r"(r[3]) : "r"(a));
}
__device__ __forceinline__ void ldmatrix_x4_trans(uint32_t* r, const __half* p) {
    uint32_t a = (uint32_t)__cvta_generic_to_shared(p);
    asm volatile("ldmatrix.sync.aligned.m8n8.x4.trans.shared.b16 {%0,%1,%2,%3}, [%4];"
                 : "=r"(r[0]), "=r"(r[1]), "=r"(r[2]), "=r"(r[3]) : "r"(a));
}
__device__ __forceinline__ void mma_16816(float* d, const uint32_t* a, const uint32_t* b) {
    asm volatile(
        "mma.sync.aligned.m16n8k16.row.col.f32.f16.f16.f32 "
        "{%0,%1,%2,%3}, {%4,%5,%6,%7}, {%8,%9}, {%0,%1,%2,%3};"
        : "+f"(d[0]), "+f"(d[1]), "+f"(d[2]), "+f"(d[3])
        : "r"(a[0]), "r"(a[1]), "r"(a[2]), "r"(a[3]), "r"(b[0]), "r"(b[1]));
}

__global__ __launch_bounds__(128) void gemm_fp16_kernel(
    const float* __restrict__ bias,
    float* __restrict__ out)
{
    extern __shared__ __half smem[];
    __shared__ int s_tile;

    const int tid  = threadIdx.x;
    const int lane = tid & 31;
    const int warpId = tid >> 5;
    const int wm = warpId >> 1;   // M offset wm*64
    const int wn = warpId & 1;    // N offset wn*64
    const int lrow = lane & 15;
    const int lcol = (lane >> 4) * 8;

    auto As = [&](int s) { return smem + s * STAGE_H; };
    auto Bs = [&](int s) { return smem + s * STAGE_H + A_STAGE_H; };

    auto load_stage = [&](int kt, int s, int row0, int col0) {
        const __half* Ag = g_A_h + (size_t)row0 * IN_DIM + kt * BK;
        const __half* Bg = g_W_h + (size_t)(kt * BK) * OUT_DIM + col0;
        __half* as = As(s);
        __half* bs = Bs(s);
        #pragma unroll
        for (int p = 0; p < 4; p++) {
            int f = tid + p * 128;
            int r = f >> 2, c = (f & 3) * 8;
            cp_async16(&as[r * LDA_S + c], Ag + (size_t)r * IN_DIM + c);
        }
        #pragma unroll
        for (int p = 0; p < 4; p++) {
            int f = tid + p * 128;
            int r = f >> 4, c = (f & 15) * 8;
            cp_async16(&bs[r * LDB_S + c], Bg + (size_t)r * OUT_DIM + c);
        }
    };

    auto fetch_ticket = [&]() -> int {
        __syncthreads();
        if (tid == 0) s_tile = atomicAdd(&g_ticket, 1);
        __syncthreads();
        return s_tile;
    };

    int t = fetch_ticket();
    if (t >= NTILES) return;
    int row0 = (t >> 5) * BM;
    int col0 = (t & 31) * BN;

    #pragma unroll
    for (int s = 0; s < STAGES - 1; s++) {
        load_stage(s, s, row0, col0);
        cp_async_commit();
    }

    while (true) {
        float acc[4][8][4];
        #pragma unroll
        for (int i = 0; i < 4; i++)
            #pragma unroll
            for (int j = 0; j < 8; j++)
                #pragma unroll
                for (int e = 0; e < 4; e++)
                    acc[i][j][e] = 0.0f;

        for (int kt = 0; kt < KT; kt++) {
            cp_async_wait<STAGES - 2>();
            __syncthreads();

            if (kt + STAGES - 1 < KT) {
                load_stage(kt + STAGES - 1, (kt + STAGES - 1) & (STAGES - 1), row0, col0);
                cp_async_commit();
            }

            const __half* Asb = As(kt & (STAGES - 1));
            const __half* Bsb = Bs(kt & (STAGES - 1));

            // ---- Batched fragment loads: BOTH ks halves before any MMA ----
            uint32_t afr[2][4][4];
            uint32_t bfr[2][4][4];
            #pragma unroll
            for (int ks = 0; ks < 2; ks++) {
                #pragma unroll
                for (int mt = 0; mt < 4; mt++)
                    ldmatrix_x4(afr[ks][mt],
                        Asb + (wm * 64 + mt * 16 + lrow) * LDA_S + ks * 16 + lcol);
                #pragma unroll
                for (int nt2 = 0; nt2 < 4; nt2++)
                    ldmatrix_x4_trans(bfr[ks][nt2],
                        Bsb + (ks * 16 + lrow) * LDB_S + wn * 64 + nt2 * 16 + lcol);
            }
            // ---- 64 MMAs ----
            #pragma unroll
            for (int ks = 0; ks < 2; ks++)
                #pragma unroll
                for (int mt = 0; mt < 4; mt++)
                    #pragma unroll
                    for (int nt = 0; nt < 8; nt++)
                        mma_16816(acc[mt][nt], afr[ks][mt], &bfr[ks][nt >> 1][(nt & 1) * 2]);
        }
        cp_async_wait<0>();   // drain before smem reuse

        // Next tile's prologue before this epilogue (loads hide under stores).
        const int erow0 = row0, ecol0 = col0;
        int t2 = fetch_ticket();     // includes barriers protecting smem reuse
        const bool more = (t2 < NTILES);
        if (more) {
            row0 = (t2 >> 5) * BM;
            col0 = (t2 & 31) * BN;
            #pragma unroll
            for (int s = 0; s < STAGES - 1; s++) {
                load_stage(s, s, row0, col0);
                cp_async_commit();
            }
        }

        // Epilogue: direct float2 stores with fused bias.
        #pragma unroll
        for (int mt = 0; mt < 4; mt++) {
            const int r = erow0 + wm * 64 + mt * 16 + (lane >> 2);
            float* o0 = out + (size_t)r * OUT_DIM;
            float* o1 = out + (size_t)(r + 8) * OUT_DIM;
            #pragma unroll
            for (int nt = 0; nt < 8; nt++) {
                const int c = ecol0 + wn * 64 + nt * 8 + 2 * (lane & 3);
                float2 bb = *reinterpret_cast<const float2*>(bias + c);
                float2 v0 = { acc[mt][nt][0] + bb.x, acc[mt][nt][1] + bb.y };
                float2 v1 = { acc[mt][nt][2] + bb.x, acc[mt][nt][3] + bb.y };
                *reinterpret_cast<float2*>(o0 + c) = v0;
                *reinterpret_cast<float2*>(o1 + c) = v1;
            }
        }

        if (!more) break;
    }
}

// ---------------------------------------------------------------------------
// Launch
// ---------------------------------------------------------------------------
extern "C" void kernel_launch(void* const* d_in, const int* in_sizes, int n_in,
                              void* d_out, int out_size) {
    const float* x    = (const float*)d_in[0];  // [2048, 4096] fp32
    const int*   idx  = (const int*)  d_in[1];  // [4096, 4096] int32
    const float* mean = (const float*)d_in[2];  // [4096] fp32
    const float* bias = (const float*)d_in[3];  // [4096] fp32
    float* out = (float*)d_out;                 // [2048, 4096] fp32

    // 1) fused prep: decode W || convert A; resets ticket
    prep_kernel<<<DEC_BLOCKS + CNV_BLOCKS, 256>>>(
        (const int4*)idx, mean, (const float4*)x);

    // 2) persistent fp16 GEMM + bias (4 warps/CTA, batched LDSM)
    cudaFuncSetAttribute(gemm_fp16_kernel,
                         cudaFuncAttributeMaxDynamicSharedMemorySize, SMEM_BYTES);
    gemm_fp16_kernel<<<NWORKERS, 128, SMEM_BYTES>>>(bias, out);
}

// round 8
// speedup vs baseline: 1.1154x; 1.1154x over previous
#include <cuda_runtime.h>
#include <cuda_fp16.h>
#include <cstdint>

// ---------------------------------------------------------------------------
// Problem dims
// ---------------------------------------------------------------------------
#define BATCH   2048
#define IN_DIM  4096   // K
#define OUT_DIM 4096   // N

// Scratch (static __device__ = sanctioned mechanism).
__device__ __align__(256) __half g_W_h[(size_t)IN_DIM * OUT_DIM];  // [K,N] fp16 (32MB)
__device__ __align__(256) __half g_A_h[(size_t)BATCH * IN_DIM];    // [M,K] fp16 (16MB)
__device__ int g_ticket;                                            // persistent-GEMM work counter

// ---------------------------------------------------------------------------
// Kernel 1 (fused prep): blocks [0,4096) decode W, [4096,8192) convert A.
// ---------------------------------------------------------------------------
#define DEC_BLOCKS 4096
#define CNV_BLOCKS 4096

__global__ __launch_bounds__(256) void prep_kernel(const int4* __restrict__ idx,
                                                   const float* __restrict__ mean,
                                                   const float4* __restrict__ x) {
    const int b = blockIdx.x;
    if (b < DEC_BLOCKS) {
        __shared__ float sm[IN_DIM];
        #pragma unroll
        for (int i = threadIdx.x; i < IN_DIM; i += 256) sm[i] = mean[i];
        __syncthreads();

        const size_t base = (size_t)b * (256 * 4) + threadIdx.x;  // int4 units
        int4 v[4];
        #pragma unroll
        for (int p = 0; p < 4; p++) v[p] = idx[base + (size_t)p * 256];
        #pragma unroll
        for (int p = 0; p < 4; p++) {
            __half2 lo = __floats2half2_rn(sm[v[p].x], sm[v[p].y]);
            __half2 hi = __floats2half2_rn(sm[v[p].z], sm[v[p].w]);
            uint2 pk;
            pk.x = *reinterpret_cast<uint32_t*>(&lo);
            pk.y = *reinterpret_cast<uint32_t*>(&hi);
            reinterpret_cast<uint2*>(g_W_h)[base + (size_t)p * 256] = pk;
        }
    } else {
        if (b == DEC_BLOCKS && threadIdx.x == 0) g_ticket = 0;  // reset before GEMM
        int t = (b - DEC_BLOCKS) * 256 + threadIdx.x;
        float4 v0 = x[2 * t];
        float4 v1 = x[2 * t + 1];
        __half2 h0 = __floats2half2_rn(v0.x, v0.y);
        __half2 h1 = __floats2half2_rn(v0.z, v0.w);
        __half2 h2 = __floats2half2_rn(v1.x, v1.y);
        __half2 h3 = __floats2half2_rn(v1.z, v1.w);
        uint4 pk;
        pk.x = *reinterpret_cast<uint32_t*>(&h0);
        pk.y = *reinterpret_cast<uint32_t*>(&h1);
        pk.z = *reinterpret_cast<uint32_t*>(&h2);
        pk.w = *reinterpret_cast<uint32_t*>(&h3);
        reinterpret_cast<uint4*>(g_A_h)[t] = pk;
    }
}

// ---------------------------------------------------------------------------
// Kernel 2: persistent fp16 GEMM (fp32 accum) + bias. mma.sync + ldmatrix.
// Block tile 128x128, 4 warps (2x2), warp tile 64x64, BK=32, 4-stage cp.async,
// 296 persistent CTAs (2/SM). Register double-buffered fragment pipeline at
// ks (half-kt) granularity: fragments for half-step h+1 are loaded by the LSU
// while the tensor pipe runs half-step h's 32 MMAs.
// ---------------------------------------------------------------------------
#define BM 128
#define BN 128
#define BK 32
#define KT (IN_DIM / BK)        // 128
#define NTILES ((BATCH / BM) * (OUT_DIM / BN))   // 512
#define NWORKERS 296
#define STAGES 4
#define LDA_S 40                // A smem row stride (halves): 80B
#define LDB_S 136               // B smem row stride (halves): 272B
#define A_STAGE_H (BM * LDA_S)  // 5120
#define B_STAGE_H (BK * LDB_S)  // 4352
#define STAGE_H   (A_STAGE_H + B_STAGE_H)
#define SMEM_BYTES (STAGES * STAGE_H * 2)   // 75776 B (2 CTAs/SM: 151KB < 228KB)

__device__ __forceinline__ void cp_async16(__half* smem_dst, const __half* gmem_src) {
    uint32_t s = (uint32_t)__cvta_generic_to_shared(smem_dst);
    asm volatile("cp.async.cg.shared.global [%0], [%1], 16;\n" :: "r"(s), "l"(gmem_src));
}
__device__ __forceinline__ void cp_async_commit() {
    asm volatile("cp.async.commit_group;\n" ::);
}
template <int N>
__device__ __forceinline__ void cp_async_wait() {
    asm volatile("cp.async.wait_group %0;\n" :: "n"(N));
}
__device__ __forceinline__ void ldmatrix_x4(uint32_t* r, const __half* p) {
    uint32_t a = (uint32_t)__cvta_generic_to_shared(p);
    asm volatile("ldmatrix.sync.aligned.m8n8.x4.shared.b16 {%0,%1,%2,%3}, [%4];"
                 : "=r"(r[0]), "=r"(r[1]), "=r"(r[2]), "=r"(r[3]) : "r"(a));
}
__device__ __forceinline__ void ldmatrix_x4_trans(uint32_t* r, const __half* p) {
    uint32_t a = (uint32_t)__cvta_generic_to_shared(p);
    asm volatile("ldmatrix.sync.aligned.m8n8.x4.trans.shared.b16 {%0,%1,%2,%3}, [%4];"
                 : "=r"(r[0]), "=r"(r[1]), "=r"(r[2]), "=r"(r[3]) : "r"(a));
}
__device__ __forceinline__ void mma_16816(float* d, const uint32_t* a, const uint32_t* b) {
    asm volatile(
        "mma.sync.aligned.m16n8k16.row.col.f32.f16.f16.f32 "
        "{%0,%1,%2,%3}, {%4,%5,%6,%7}, {%8,%9}, {%0,%1,%2,%3};"
        : "+f"(d[0]), "+f"(d[1]), "+f"(d[2]), "+f"(d[3])
        : "r"(a[0]), "r"(a[1]), "r"(a[2]), "r"(a[3]), "r"(b[0]), "r"(b[1]));
}

__global__ __launch_bounds__(128, 2) void gemm_fp16_kernel(
    const float* __restrict__ bias,
    float* __restrict__ out)
{
    extern __shared__ __half smem[];
    __shared__ int s_tile;

    const int tid  = threadIdx.x;
    const int lane = tid & 31;
    const int warpId = tid >> 5;
    const int wm = warpId >> 1;   // M offset wm*64
    const int wn = warpId & 1;    // N offset wn*64
    const int lrow = lane & 15;
    const int lcol = (lane >> 4) * 8;

    auto As = [&](int s) { return smem + s * STAGE_H; };
    auto Bs = [&](int s) { return smem + s * STAGE_H + A_STAGE_H; };

    auto load_stage = [&](int kt, int s, int row0, int col0) {
        const __half* Ag = g_A_h + (size_t)row0 * IN_DIM + kt * BK;
        const __half* Bg = g_W_h + (size_t)(kt * BK) * OUT_DIM + col0;
        __half* as = As(s);
        __half* bs = Bs(s);
        #pragma unroll
        for (int p = 0; p < 4; p++) {
            int f = tid + p * 128;
            int r = f >> 2, c = (f & 3) * 8;
            cp_async16(&as[r * LDA_S + c], Ag + (size_t)r * IN_DIM + c);
        }
        #pragma unroll
        for (int p = 0; p < 4; p++) {
            int f = tid + p * 128;
            int r = f >> 4, c = (f & 15) * 8;
            cp_async16(&bs[r * LDB_S + c], Bg + (size_t)r * OUT_DIM + c);
        }
    };

    auto fetch_ticket = [&]() -> int {
        __syncthreads();
        if (tid == 0) s_tile = atomicAdd(&g_ticket, 1);
        __syncthreads();
        return s_tile;
    };

    int t = fetch_ticket();
    if (t >= NTILES) return;
    int row0 = (t >> 5) * BM;
    int col0 = (t & 31) * BN;

    // Fragment double buffers (ping-pong at ks granularity)
    uint32_t afr[2][4][4];
    uint32_t bfr[2][4][4];

    auto ldsm_half = [&](int buf, const __half* Asb, const __half* Bsb, int ks) {
        #pragma unroll
        for (int mt = 0; mt < 4; mt++)
            ldmatrix_x4(afr[buf][mt],
                Asb + (wm * 64 + mt * 16 + lrow) * LDA_S + ks * 16 + lcol);
        #pragma unroll
        for (int nt2 = 0; nt2 < 4; nt2++)
            ldmatrix_x4_trans(bfr[buf][nt2],
                Bsb + (ks * 16 + lrow) * LDB_S + wn * 64 + nt2 * 16 + lcol);
    };

    // Prologue for first tile: issue stages 0..2
    #pragma unroll
    for (int s = 0; s < STAGES - 1; s++) {
        load_stage(s, s, row0, col0);
        cp_async_commit();
    }

    while (true) {
        float acc[4][8][4];
        #pragma unroll
        for (int i = 0; i < 4; i++)
            #pragma unroll
            for (int j = 0; j < 8; j++)
                #pragma unroll
                for (int e = 0; e < 4; e++)
                    acc[i][j][e] = 0.0f;

        // Tile init: stage 0 resident, preload (kt=0, ks=0) fragments.
        cp_async_wait<STAGES - 2>();
        __syncthreads();
        ldsm_half(0, As(0), Bs(0), 0);

        for (int kt = 0; kt < KT; kt++) {
            const int slot = kt & (STAGES - 1);
            const __half* Asb = As(slot);
            const __half* Bsb = Bs(slot);
            const int cur = 0, nxt = 1;   // buffer roles fixed per kt (two half-steps)

            // LDSM (kt, ks1) -> nxt; overlaps with MMA(ks0) below (no dependency)
            ldsm_half(nxt, Asb, Bsb, 1);

            // MMA half-block ks0 on cur
            #pragma unroll
            for (int mt = 0; mt < 4; mt++)
                #pragma unroll
                for (int nt = 0; nt < 8; nt++)
                    mma_16816(acc[mt][nt], afr[cur][mt], &bfr[cur][nt >> 1][(nt & 1) * 2]);

            if (kt + 1 < KT) {
                // Stage kt+1 must be resident before prefetching its fragments.
                if (kt + 2 < KT) cp_async_wait<1>();
                else             cp_async_wait<0>();
                __syncthreads();   // visibility of other threads' cp.async + slot-reuse guard
                // Refill the pipeline depth (overwrites slot of stage kt-1; its
                // LDSMs completed before the PREVIOUS iteration's barrier).
                if (kt + STAGES - 1 < KT) {
                    load_stage(kt + STAGES - 1, (kt + STAGES - 1) & (STAGES - 1), row0, col0);
                    cp_async_commit();
                }
                // LDSM (kt+1, ks0) -> cur; overlaps with MMA(ks1) below
                ldsm_half(cur, As((kt + 1) & (STAGES - 1)), Bs((kt + 1) & (STAGES - 1)), 0);
            }

            // MMA half-block ks1 on nxt
            #pragma unroll
            for (int mt = 0; mt < 4; mt++)
                #pragma unroll
                for (int nt = 0; nt < 8; nt++)
                    mma_16816(acc[mt][nt], afr[nxt][mt], &bfr[nxt][nt >> 1][(nt & 1) * 2]);
        }
        cp_async_wait<0>();

        // Next tile's prologue before this epilogue (loads hide under stores).
        const int erow0 = row0, ecol0 = col0;
        int t2 = fetch_ticket();     // barriers protect smem reuse
        const bool more = (t2 < NTILES);
        if (more) {
            row0 = (t2 >> 5) * BM;
            col0 = (t2 & 31) * BN;
            #pragma unroll
            for (int s = 0; s < STAGES - 1; s++) {
                load_stage(s, s, row0, col0);
                cp_async_commit();
            }
        }

        // Epilogue: direct float2 stores with fused bias.
        #pragma unroll
        for (int mt = 0; mt < 4; mt++) {
            const int r = erow0 + wm * 64 + mt * 16 + (lane >> 2);
            float* o0 = out + (size_t)r * OUT_DIM;
            float* o1 = out + (size_t)(r + 8) * OUT_DIM;
            #pragma unroll
            for (int nt = 0; nt < 8; nt++) {
                const int c = ecol0 + wn * 64 + nt * 8 + 2 * (lane & 3);
                float2 bb = *reinterpret_cast<const float2*>(bias + c);
                float2 v0 = { acc[mt][nt][0] + bb.x, acc[mt][nt][1] + bb.y };
                float2 v1 = { acc[mt][nt][2] + bb.x, acc[mt][nt][3] + bb.y };
                *reinterpret_cast<float2*>(o0 + c) = v0;
                *reinterpret_cast<float2*>(o1 + c) = v1;
            }
        }

        if (!more) break;
    }
}

// ---------------------------------------------------------------------------
// Launch
// ---------------------------------------------------------------------------
extern "C" void kernel_launch(void* const* d_in, const int* in_sizes, int n_in,
                              void* d_out, int out_size) {
    const float* x    = (const float*)d_in[0];  // [2048, 4096] fp32
    const int*   idx  = (const int*)  d_in[1];  // [4096, 4096] int32
    const float* mean = (const float*)d_in[2];  // [4096] fp32
    const float* bias = (const float*)d_in[3];  // [4096] fp32
    float* out = (float*)d_out;                 // [2048, 4096] fp32

    // 1) fused prep: decode W || convert A; resets ticket
    prep_kernel<<<DEC_BLOCKS + CNV_BLOCKS, 256>>>(
        (const int4*)idx, mean, (const float4*)x);

    // 2) persistent fp16 GEMM + bias (register-pipelined fragments)
    cudaFuncSetAttribute(gemm_fp16_kernel,
                         cudaFuncAttributeMaxDynamicSharedMemorySize, SMEM_BYTES);
    gemm_fp16_kernel<<<NWORKERS, 128, SMEM_BYTES>>>(bias, out);
}